// round 10
// baseline (speedup 1.0000x reference)
#include <cuda_runtime.h>
#include <math.h>

// Fixed problem shapes
#define BB    8
#define NA    5
#define NC    8
#define NH    192
#define NW    192
#define TT    50
#define ATTRS 15                 // 7 + NC
#define NHW   (NH*NW)            // 36864
#define CELLS (BB*NA*NHW)        // 1,474,560
#define NT    (BB*TT)            // 400
#define NIGN  (NT*NA)            // 2000
#define NPAIR (BB*TT*TT)         // 20000 ordered pairs

#define TPB       256
#define CPT       4
#define NB_DENSE  (CELLS/(CPT*TPB))   // 1440 (exact)
#define NB_TOTAL  (NB_DENSE+1)        // 1441: bid 0 = special, 1..1440 dense
#define HASH_SZ   4096                // > max 2400 inserts
#define HASH_MASK (HASH_SZ-1)
#define NWARP     (TPB/32)            // 8

typedef unsigned long long u64;

// ---- persistent device scratch ----
__device__ double   g_S0 = 0.0;
__device__ float    g_cr0, g_cr1, g_cr2, g_cr3, g_cr4, g_cr5, g_cr6;
__device__ int      g_nObjG, g_removedG;
__device__ unsigned g_ticket = 0;
__device__ unsigned g_gen = 1;              // generation for hash validity; ++ per run
__device__ u64      g_hash[HASH_SZ];        // gen<<32 | cell  (zero-init: gen 0 invalid)
__device__ int      g_meta[NT];             // special-block private (same SM across syncthreads)
__device__ unsigned char g_loser[NT];

__device__ __forceinline__ float sp_fast(float v) {   // softplus == bce0 (clip never binds, |v|<16)
    return fmaxf(v, 0.f) + __logf(1.f + __expf(-fabsf(v)));
}
__device__ __forceinline__ float sigf(float v) {
    return 1.f / (1.f + __expf(-v));
}
__device__ __forceinline__ unsigned hash_cell(int cell) {
    return (((unsigned)cell * 2654435761u) >> 16) & HASH_MASK;
}

// insert cell into generation-tagged global hash.
// returns true if this thread claimed the slot (first inserter of this cell this run).
__device__ __forceinline__ bool hash_insert(int cell, unsigned gen) {
    const u64 want = ((u64)gen << 32) | (unsigned)cell;
    volatile u64* vh = (volatile u64*)g_hash;
    unsigned h = hash_cell(cell);
    while (true) {
        u64 cur = vh[h];                        // volatile: L2-coherent view
        if (cur == want) return false;          // already present (obj or dup)
        if ((unsigned)(cur >> 32) == gen) {     // occupied by different cell
            h = (h + 1) & HASH_MASK;
            continue;
        }
        u64 prev = atomicCAS(&g_hash[h], cur, want);
        if (prev == cur) return true;           // claimed
        // slot changed under us -> retry same slot
    }
}

__global__ void __launch_bounds__(TPB)
fused(const float* __restrict__ x,
      const float* __restrict__ tg,
      const float* __restrict__ anchors,
      float* __restrict__ out)
{
    __shared__ float s_red[NWARP][8];           // tiny: dense blocks stay lean
    __shared__ int   s_cnt[2];                  // nObj, nIgn (special block only)

    const int tid  = threadIdx.x;
    const int bid  = blockIdx.x;
    const int lane = tid & 31;
    const int wid  = tid >> 5;

    if (bid != 0) {
        // ========== dense: softplus sum over conf channel (R3-proven shape) ==========
        int c0 = ((bid - 1) * TPB + tid) * CPT;
        int i0 = c0 % NW;
        int j  = (c0 / NW) % NH;
        int ba = c0 / NHW;
        float4 v = *(const float4*)(x + ((size_t)ba * ATTRS + 6) * NHW + (size_t)j * NW + i0);
        float local = sp_fast(v.x) + sp_fast(v.y) + sp_fast(v.z) + sp_fast(v.w);

        #pragma unroll
        for (int o = 16; o; o >>= 1) local += __shfl_down_sync(0xffffffffu, local, o);
        if (lane == 0) s_red[wid][0] = local;
        __syncthreads();
        if (tid == 0) {
            float bs = 0.f;
            #pragma unroll
            for (int w = 0; w < NWARP; w++) bs += s_red[w][0];
            atomicAdd(&g_S0, (double)bs);       // one REDG.F64 per block
        }
    } else {
        // ========== special block (bid 0, wave 1): sparse path via global scratch ==========
        float a0 = 0.f, a1 = 0.f, a2 = 0.f, a3 = 0.f, a4 = 0.f, a5 = 0.f, a6 = 0.f;
        float r_fx[2], r_fy[2], r_tw[2], r_th[2];
        int   r_label[2];
        float aw_[NA], ah_[NA];
        #pragma unroll
        for (int a = 0; a < NA; a++) { aw_[a] = anchors[2*a]; ah_[a] = anchors[2*a+1]; }
        const unsigned gen = *(volatile unsigned*)&g_gen;

        for (int i = tid; i < NT; i += TPB) g_loser[i] = 0;
        if (tid < 2) s_cnt[tid] = 0;

        // phase 0: per-target precompute (2 register slots per thread)
        #pragma unroll
        for (int it = 0; it < 2; it++) {
            int t = tid + it * TPB;
            if (t < NT) {
                const float* r = tg + (size_t)t * 5;
                float r0 = r[0], r1 = r[1], r2 = r[2], r3 = r[3], r4 = r[4];
                int valid = ((r0 + r1 + r2 + r3 + r4) != 0.f);
                float gx = r1 * NW, gy = r2 * NH, gw = r3 * NW, gh = r4 * NH;
                int gi = (int)floorf(gx), gj = (int)floorf(gy);
                float bestIou = -1.f; int best = 0; float awb = 1.f, ahb = 1.f;
                #pragma unroll
                for (int a = 0; a < NA; a++) {
                    float inter = fminf(gw, aw_[a]) * fminf(gh, ah_[a]);
                    float iou   = inter / (gw * gh + aw_[a] * ah_[a] - inter);
                    if (iou > bestIou) { bestIou = iou; best = a; awb = aw_[a]; ahb = ah_[a]; }
                }
                g_meta[t]   = (valid << 28) | (best << 16) | (gj << 8) | gi;
                r_label[it] = (int)r0;
                r_fx[it] = gx - floorf(gx);
                r_fy[it] = gy - floorf(gy);
                r_tw[it] = __logf(gw / awb + 1e-16f);
                r_th[it] = __logf(gh / ahb + 1e-16f);
            }
        }
        __syncthreads();

        // phase 0.5: parallel last-write-wins — mark losers via pair comparisons
        for (int p = tid; p < NPAIR; p += TPB) {
            int b  = p / (TT*TT);
            int r  = p - b * (TT*TT);
            int ti = r / TT;
            int tj = r - ti * TT;
            if (tj > ti) {
                int t1 = b * TT + ti, t2 = b * TT + tj;
                int m1 = g_meta[t1];
                if ((m1 >> 28) && m1 == g_meta[t2]) g_loser[t1] = 1;   // benign race
            }
        }
        __syncthreads();

        // phase 1: winners -> hash insert + obj-cell work
        #pragma unroll
        for (int it = 0; it < 2; it++) {
            int t = tid + it * TPB;
            if (t < NT) {
                int meta = g_meta[t];
                if ((meta >> 28) && !g_loser[t]) {
                    int b = t / TT;
                    int best = (meta >> 16) & 0xff, gj = (meta >> 8) & 0xff, gi = meta & 0xff;
                    int cell = ((b * NA + best) * NH + gj) * NW + gi;
                    hash_insert(cell, gen);     // winners are unique -> always claims
                    atomicAdd(&s_cnt[0], 1);

                    size_t base = (size_t)(b * NA + best) * ATTRS * NHW + (size_t)gj * NW + gi;
                    float x0 = x[base];
                    float x1 = x[base + (size_t)NHW];
                    float x2 = x[base + 2 * (size_t)NHW];
                    float x3 = x[base + 3 * (size_t)NHW];
                    float xc = x[base + 6 * (size_t)NHW];

                    float dx = sigf(x0) - r_fx[it];
                    float dy = sigf(x1) - r_fy[it];
                    float dw = x2 - r_tw[it];
                    float dh = x3 - r_th[it];
                    a2 += dx * dx;
                    a3 += dy * dy;
                    a4 += dw * dw;
                    a5 += dh * dh;
                    a1 += sp_fast(-xc);             // -log p (tconf=1 bce)
                    a0 -= sp_fast(xc);              // remove bce0 from noobj sum

                    float sv[NC]; float m = -1e30f;
                    #pragma unroll
                    for (int c = 0; c < NC; c++) {
                        sv[c] = sigf(x[base + (size_t)(7 + c) * NHW]);
                        m = fmaxf(m, sv[c]);
                    }
                    float sum = 0.f;
                    #pragma unroll
                    for (int c = 0; c < NC; c++) sum += __expf(sv[c] - m);
                    a6 += m + __logf(sum) - sv[r_label[it]];
                }
            }
        }
        __syncthreads();   // all obj cells inserted before ignore probes

        // phase 2: ignore cells (iou > 0.6); dedup via hash; obj beats ignore
        for (int k = tid; k < NIGN; k += TPB) {
            int t = k / NA, a = k - (k / NA) * NA;
            int meta = g_meta[t];
            if (!(meta >> 28)) continue;
            float gw = tg[(size_t)t * 5 + 3] * NW;
            float gh = tg[(size_t)t * 5 + 4] * NH;
            float inter = fminf(gw, aw_[a]) * fminf(gh, ah_[a]);
            float iou   = inter / (gw * gh + aw_[a] * ah_[a] - inter);
            if (!(iou > 0.6f)) continue;
            int b = t / TT, gj = (meta >> 8) & 0xff, gi = meta & 0xff;
            int cell = ((b * NA + a) * NH + gj) * NW + gi;
            if (!hash_insert(cell, gen)) continue;      // dup or obj cell
            atomicAdd(&s_cnt[1], 1);
            float xc = x[((size_t)(b * NA + a) * ATTRS + 6) * NHW + (size_t)gj * NW + gi];
            a0 -= sp_fast(xc);
        }

        // block reduction in float
        #pragma unroll
        for (int o = 16; o; o >>= 1) {
            a0 += __shfl_down_sync(0xffffffffu, a0, o);
            a1 += __shfl_down_sync(0xffffffffu, a1, o);
            a2 += __shfl_down_sync(0xffffffffu, a2, o);
            a3 += __shfl_down_sync(0xffffffffu, a3, o);
            a4 += __shfl_down_sync(0xffffffffu, a4, o);
            a5 += __shfl_down_sync(0xffffffffu, a5, o);
            a6 += __shfl_down_sync(0xffffffffu, a6, o);
        }
        if (lane == 0) {
            s_red[wid][0] = a0; s_red[wid][1] = a1; s_red[wid][2] = a2;
            s_red[wid][3] = a3; s_red[wid][4] = a4; s_red[wid][5] = a5;
            s_red[wid][6] = a6;
        }
        __syncthreads();
        if (tid == 0) {
            float c0 = 0.f, c1 = 0.f, c2 = 0.f, c3 = 0.f, c4 = 0.f, c5 = 0.f, c6 = 0.f;
            #pragma unroll
            for (int w = 0; w < NWARP; w++) {
                c0 += s_red[w][0]; c1 += s_red[w][1]; c2 += s_red[w][2];
                c3 += s_red[w][3]; c4 += s_red[w][4]; c5 += s_red[w][5];
                c6 += s_red[w][6];
            }
            g_cr0 = c0; g_cr1 = c1; g_cr2 = c2; g_cr3 = c3;
            g_cr4 = c4; g_cr5 = c5; g_cr6 = c6;
            g_nObjG    = s_cnt[0];
            g_removedG = s_cnt[0] + s_cnt[1];
        }
    }

    // ========== ticket: last block finalizes ==========
    __syncthreads();
    if (tid == 0) {
        __threadfence();
        unsigned old = atomicAdd(&g_ticket, 1u);
        if (old == (unsigned)(NB_TOTAL - 1)) {
            double S0   = atomicAdd(&g_S0, 0.0) + (double)*(volatile float*)&g_cr0;
            double nobj = (double)*(volatile int*)&g_nObjG;
            double cnt  = (double)CELLS - (double)*(volatile int*)&g_removedG;
            double objs = (double)*(volatile float*)&g_cr2 + (double)*(volatile float*)&g_cr3
                        + (double)*(volatile float*)&g_cr4 + (double)*(volatile float*)&g_cr5
                        + (double)*(volatile float*)&g_cr1
                        + (double)*(volatile float*)&g_cr6 / (double)BB;
            out[0] = (float)(objs / nobj + S0 / cnt);
            g_S0 = 0.0;
            g_ticket = 0u;
            g_gen = *(volatile unsigned*)&g_gen + 1u;   // invalidate hash for next run
        }
    }
}

extern "C" void kernel_launch(void* const* d_in, const int* in_sizes, int n_in,
                              void* d_out, int out_size) {
    const float* x  = (const float*)d_in[0];
    const float* tg = (const float*)d_in[1];
    const float* an = (const float*)d_in[2];
    fused<<<NB_TOTAL, TPB>>>(x, tg, an, (float*)d_out);
}

// round 11
// speedup vs baseline: 1.6628x; 1.6628x over previous
#include <cuda_runtime.h>
#include <math.h>

// Fixed problem shapes
#define BB    8
#define NA    5
#define NC    8
#define NH    192
#define NW    192
#define TT    50
#define ATTRS 15                 // 7 + NC
#define NHW   (NH*NW)            // 36864
#define CELLS (BB*NA*NHW)        // 1,474,560
#define NT    (BB*TT)            // 400
#define NIGN  (NT*NA)            // 2000
#define NPAIR (BB*TT*TT)         // 20000 ordered pairs

#define SPB       1024                // sparse kernel block size
#define TPB       256                 // dense kernel block size
#define CPT       4
#define NB_DENSE  (CELLS/(CPT*TPB))   // 1440 (exact)
#define HASH_SZ   4096
#define HASH_MASK (HASH_SZ-1)

// ---- persistent device scratch (finisher resets -> replay-safe) ----
__device__ double   g_S0 = 0.0;
__device__ float    g_cr0, g_cr1, g_cr2, g_cr3, g_cr4, g_cr5, g_cr6;
__device__ int      g_nObjG, g_removedG;
__device__ unsigned g_ticket = 0;

__device__ __forceinline__ float sp_fast(float v) {   // softplus == bce0 (clip never binds, |v|<16)
    return fmaxf(v, 0.f) + __logf(1.f + __expf(-fabsf(v)));
}
__device__ __forceinline__ float sigf(float v) {
    return 1.f / (1.f + __expf(-v));
}
__device__ __forceinline__ unsigned hash_cell(int cell) {
    return (((unsigned)cell * 2654435761u) >> 16) & HASH_MASK;
}

// ================= Node 1: sparse path, 1 block x 1024 threads =================
__global__ void __launch_bounds__(SPB)
k_sparse(const float* __restrict__ x,
         const float* __restrict__ tg,
         const float* __restrict__ anchors)
{
    __shared__ int   s_hash[HASH_SZ];
    __shared__ int   s_meta[NT];      // valid<<28 | best<<16 | gj<<8 | gi
    __shared__ int   s_label[NT];
    __shared__ unsigned char s_loser[NT];
    __shared__ float s_fx[NT], s_fy[NT], s_tw[NT], s_th[NT], s_gw[NT], s_gh[NT];
    __shared__ float s_red[SPB/32][8];
    __shared__ int   s_nObj, s_nIgn;
    __shared__ float s_anchor[2*NA];

    const int tid  = threadIdx.x;
    const int lane = tid & 31;
    const int wid  = tid >> 5;

    float a0 = 0.f, a1 = 0.f, a2 = 0.f, a3 = 0.f, a4 = 0.f, a5 = 0.f, a6 = 0.f;

    for (int i = tid; i < HASH_SZ; i += SPB) s_hash[i] = -1;
    if (tid < NT) s_loser[tid] = 0;
    if (tid == 0) { s_nObj = 0; s_nIgn = 0; }
    if (tid < 2*NA) s_anchor[tid] = anchors[tid];
    __syncthreads();

    // phase 0: one thread per target
    if (tid < NT) {
        const int t = tid;
        const float* r = tg + (size_t)t * 5;
        float r0 = r[0], r1 = r[1], r2 = r[2], r3 = r[3], r4 = r[4];
        int valid = ((r0 + r1 + r2 + r3 + r4) != 0.f);
        float gx = r1 * NW, gy = r2 * NH, gw = r3 * NW, gh = r4 * NH;
        int gi = (int)floorf(gx), gj = (int)floorf(gy);
        float bestIou = -1.f; int best = 0; float awb = 1.f, ahb = 1.f;
        #pragma unroll
        for (int a = 0; a < NA; a++) {
            float aw = s_anchor[2*a], ah = s_anchor[2*a+1];
            float inter = fminf(gw, aw) * fminf(gh, ah);
            float iou   = inter / (gw * gh + aw * ah - inter);
            if (iou > bestIou) { bestIou = iou; best = a; awb = aw; ahb = ah; }
        }
        s_meta[t]  = (valid << 28) | (best << 16) | (gj << 8) | gi;
        s_label[t] = (int)r0;
        s_fx[t] = gx - floorf(gx);
        s_fy[t] = gy - floorf(gy);
        s_tw[t] = __logf(gw / awb + 1e-16f);
        s_th[t] = __logf(gh / ahb + 1e-16f);
        s_gw[t] = gw; s_gh[t] = gh;
    }
    __syncthreads();

    // phase 0.5: parallel last-write-wins — mark losers via pair comparisons
    for (int p = tid; p < NPAIR; p += SPB) {
        int b  = p / (TT*TT);
        int r  = p - b * (TT*TT);
        int ti = r / TT;
        int tj = r - ti * TT;
        if (tj > ti) {
            int t1 = b * TT + ti, t2 = b * TT + tj;
            int m1 = s_meta[t1];
            if ((m1 >> 28) && m1 == s_meta[t2]) s_loser[t1] = 1;  // benign race
        }
    }
    __syncthreads();

    // phase 1: winners -> hash insert + obj-cell work
    if (tid < NT) {
        const int t = tid;
        int meta = s_meta[t];
        if ((meta >> 28) && !s_loser[t]) {
            int b = t / TT;
            int best = (meta >> 16) & 0xff, gj = (meta >> 8) & 0xff, gi = meta & 0xff;
            int cell = ((b * NA + best) * NH + gj) * NW + gi;
            unsigned h = hash_cell(cell);
            while (atomicCAS(&s_hash[h], -1, cell) != -1) h = (h + 1) & HASH_MASK;
            atomicAdd(&s_nObj, 1);

            size_t base = (size_t)(b * NA + best) * ATTRS * NHW + (size_t)gj * NW + gi;
            float x0 = x[base];
            float x1 = x[base + (size_t)NHW];
            float x2 = x[base + 2 * (size_t)NHW];
            float x3 = x[base + 3 * (size_t)NHW];
            float xc = x[base + 6 * (size_t)NHW];

            float dx = sigf(x0) - s_fx[t];
            float dy = sigf(x1) - s_fy[t];
            float dw = x2 - s_tw[t];
            float dh = x3 - s_th[t];
            a2 += dx * dx;
            a3 += dy * dy;
            a4 += dw * dw;
            a5 += dh * dh;
            a1 += sp_fast(-xc);                 // -log p (tconf=1 bce)
            a0 -= sp_fast(xc);                  // remove bce0 from noobj sum

            float sv[NC]; float m = -1e30f;
            #pragma unroll
            for (int c = 0; c < NC; c++) {
                sv[c] = sigf(x[base + (size_t)(7 + c) * NHW]);
                m = fmaxf(m, sv[c]);
            }
            float sum = 0.f;
            #pragma unroll
            for (int c = 0; c < NC; c++) sum += __expf(sv[c] - m);
            a6 += m + __logf(sum) - sv[s_label[t]];
        }
    }
    __syncthreads();   // all obj cells in hash before ignore probes

    // phase 2: ignore cells (iou > 0.6), dedup via hash; obj beats ignore
    for (int k = tid; k < NIGN; k += SPB) {
        int t = k / NA, a = k - (k / NA) * NA;
        int meta = s_meta[t];
        if (!(meta >> 28)) continue;
        float aw = s_anchor[2*a], ah = s_anchor[2*a+1];
        float gw = s_gw[t], gh = s_gh[t];
        float inter = fminf(gw, aw) * fminf(gh, ah);
        float iou   = inter / (gw * gh + aw * ah - inter);
        if (!(iou > 0.6f)) continue;
        int b = t / TT, gj = (meta >> 8) & 0xff, gi = meta & 0xff;
        int cell = ((b * NA + a) * NH + gj) * NW + gi;
        unsigned h = hash_cell(cell);
        bool mine = false;
        while (true) {
            int prev = atomicCAS(&s_hash[h], -1, cell);
            if (prev == -1)   { mine = true; break; }
            if (prev == cell) break;            // dup or obj cell
            h = (h + 1) & HASH_MASK;
        }
        if (!mine) continue;
        atomicAdd(&s_nIgn, 1);
        float xc = x[((size_t)(b * NA + a) * ATTRS + 6) * NHW + (size_t)gj * NW + gi];
        a0 -= sp_fast(xc);
    }

    // block reduction in float
    #pragma unroll
    for (int o = 16; o; o >>= 1) {
        a0 += __shfl_down_sync(0xffffffffu, a0, o);
        a1 += __shfl_down_sync(0xffffffffu, a1, o);
        a2 += __shfl_down_sync(0xffffffffu, a2, o);
        a3 += __shfl_down_sync(0xffffffffu, a3, o);
        a4 += __shfl_down_sync(0xffffffffu, a4, o);
        a5 += __shfl_down_sync(0xffffffffu, a5, o);
        a6 += __shfl_down_sync(0xffffffffu, a6, o);
    }
    if (lane == 0) {
        s_red[wid][0] = a0; s_red[wid][1] = a1; s_red[wid][2] = a2;
        s_red[wid][3] = a3; s_red[wid][4] = a4; s_red[wid][5] = a5;
        s_red[wid][6] = a6;
    }
    __syncthreads();
    if (tid == 0) {
        float c0 = 0.f, c1 = 0.f, c2 = 0.f, c3 = 0.f, c4 = 0.f, c5 = 0.f, c6 = 0.f;
        #pragma unroll
        for (int w = 0; w < SPB/32; w++) {
            c0 += s_red[w][0]; c1 += s_red[w][1]; c2 += s_red[w][2];
            c3 += s_red[w][3]; c4 += s_red[w][4]; c5 += s_red[w][5];
            c6 += s_red[w][6];
        }
        g_cr0 = c0; g_cr1 = c1; g_cr2 = c2; g_cr3 = c3;
        g_cr4 = c4; g_cr5 = c5; g_cr6 = c6;
        g_nObjG    = s_nObj;
        g_removedG = s_nObj + s_nIgn;
    }
}

// ================= Node 2: dense softplus sum + ticket finalize =================
__global__ void __launch_bounds__(TPB)
k_dense(const float* __restrict__ x, float* __restrict__ out)
{
    __shared__ float s_warp[TPB/32];
    const int tid  = threadIdx.x;
    const int lane = tid & 31;
    const int wid  = tid >> 5;

    int c0 = (blockIdx.x * TPB + tid) * CPT;
    int i0 = c0 % NW;
    int j  = (c0 / NW) % NH;
    int ba = c0 / NHW;
    float4 v = *(const float4*)(x + ((size_t)ba * ATTRS + 6) * NHW + (size_t)j * NW + i0);
    float local = sp_fast(v.x) + sp_fast(v.y) + sp_fast(v.z) + sp_fast(v.w);

    #pragma unroll
    for (int o = 16; o; o >>= 1) local += __shfl_down_sync(0xffffffffu, local, o);
    if (lane == 0) s_warp[wid] = local;
    __syncthreads();

    if (tid == 0) {
        float bs = 0.f;
        #pragma unroll
        for (int w = 0; w < TPB/32; w++) bs += s_warp[w];
        atomicAdd(&g_S0, (double)bs);               // REDG.F64
        __threadfence();
        unsigned old = atomicAdd(&g_ticket, 1u);
        if (old == (unsigned)(NB_DENSE - 1)) {      // last dense block: finalize
            double S0   = atomicAdd(&g_S0, 0.0) + (double)*(volatile float*)&g_cr0;
            double nobj = (double)*(volatile int*)&g_nObjG;
            double cnt  = (double)CELLS - (double)*(volatile int*)&g_removedG;
            double objs = (double)*(volatile float*)&g_cr2 + (double)*(volatile float*)&g_cr3
                        + (double)*(volatile float*)&g_cr4 + (double)*(volatile float*)&g_cr5
                        + (double)*(volatile float*)&g_cr1
                        + (double)*(volatile float*)&g_cr6 / (double)BB;
            out[0] = (float)(objs / nobj + S0 / cnt);
            g_S0 = 0.0;                             // replay-safe reset
            g_ticket = 0u;
        }
    }
}

extern "C" void kernel_launch(void* const* d_in, const int* in_sizes, int n_in,
                              void* d_out, int out_size) {
    const float* x  = (const float*)d_in[0];
    const float* tg = (const float*)d_in[1];
    const float* an = (const float*)d_in[2];
    k_sparse<<<1, SPB>>>(x, tg, an);
    k_dense<<<NB_DENSE, TPB>>>(x, (float*)d_out);
}